// round 1
// baseline (speedup 1.0000x reference)
#include <cuda_runtime.h>
#include <cuda_bf16.h>

// MeanMemoryMessageReducer: segment mean of messages + last timestamp per segment.
// segment_ids is SORTED, so each segment is a contiguous row range found by
// binary search. One CTA (128 threads) per segment; thread t owns column t.
//
// Inputs (metadata order):
//   d_in[0] unique_nids  int32   [M]
//   d_in[1] messages     float32 [N, 128]
//   d_in[2] timestamps   float32 [N]
//   d_in[3] segment_ids  int32   [N]   (sorted ascending, values in [0, M))
//   (num_segments may appear as a scalar input; we derive M from in_sizes[0])
//
// Output (float32, flattened tuple):
//   [0, M)            unique_nids cast to float
//   [M, M + M*128)    segment means (0 for empty segments)
//   [M + M*128, +M)   last timestamp per segment (timestamps[0] for empty:
//                     reference clips segment_max's INT_MIN fill to 0)

#define D 128

__global__ __launch_bounds__(D) void seg_mean_kernel(
    const int* __restrict__ nids,
    const float* __restrict__ msgs,
    const float* __restrict__ ts,
    const int* __restrict__ seg,
    float* __restrict__ out,
    int N, int M)
{
    const int s = blockIdx.x;
    __shared__ int sh_bounds[2];

    if (threadIdx.x < 2) {
        // lower_bound(seg, s + threadIdx.x): first index with seg[i] >= target
        const int target = s + (int)threadIdx.x;
        int lo = 0, hi = N;
        while (lo < hi) {
            int mid = (lo + hi) >> 1;
            if (seg[mid] < target) lo = mid + 1; else hi = mid;
        }
        sh_bounds[threadIdx.x] = lo;
    }
    __syncthreads();

    const int start = sh_bounds[0];
    const int end   = sh_bounds[1];
    const int cnt   = end - start;

    float acc = 0.0f;
    const float* p = msgs + (long long)start * D + threadIdx.x;
    for (int r = 0; r < cnt; ++r) {
        acc += *p;
        p += D;
    }

    const float denom = fmaxf((float)cnt, 1.0f);
    out[(long long)M + (long long)s * D + threadIdx.x] = acc / denom;

    if (threadIdx.x == 0) {
        out[s] = (float)nids[s];
        const int last_idx = (cnt > 0) ? (end - 1) : 0;
        out[(long long)M + (long long)M * D + s] = ts[last_idx];
    }
}

extern "C" void kernel_launch(void* const* d_in, const int* in_sizes, int n_in,
                              void* d_out, int out_size)
{
    const int*   nids = (const int*)d_in[0];
    const float* msgs = (const float*)d_in[1];
    const float* ts   = (const float*)d_in[2];
    const int*   seg  = (const int*)d_in[3];
    float* out = (float*)d_out;

    const int M = in_sizes[0];      // number of segments
    const int N = in_sizes[2];      // number of messages (timestamps count)

    seg_mean_kernel<<<M, D>>>(nids, msgs, ts, seg, out, N, M);
}

// round 2
// speedup vs baseline: 2.8293x; 2.8293x over previous
#include <cuda_runtime.h>
#include <cuda_bf16.h>

// MeanMemoryMessageReducer — segment mean + last timestamp, sorted segment_ids.
//
// 3-kernel pipeline:
//   K1 bounds_kernel : bounds[s] = lower_bound(seg, s) for s in [0, M]  (1 thread/segment)
//   K2 mean_kernel   : warp-per-segment, float4 row loads (512B/warp/iter), no barriers
//   K3 epi_kernel    : nids cast + last-timestamp gather (monotonic -> coalesced)
//
// Output layout (float32): [ nids(M) | means(M*128) | last_ts(M) ]

#define DCOLS 128
#define MAX_M (1 << 20)

__device__ int g_bounds[MAX_M + 1];

__global__ __launch_bounds__(256) void bounds_kernel(
    const int* __restrict__ seg, int N, int M)
{
    const int s = blockIdx.x * blockDim.x + threadIdx.x;
    if (s > M) return;
    // lower_bound: first index with seg[i] >= s
    int lo = 0, hi = N;
    while (lo < hi) {
        int mid = (lo + hi) >> 1;
        if (seg[mid] < s) lo = mid + 1; else hi = mid;
    }
    g_bounds[s] = lo;
}

__global__ __launch_bounds__(256) void mean_kernel(
    const float* __restrict__ msgs,
    float* __restrict__ out_means,   // out + M
    int M)
{
    const int warp = (int)((blockIdx.x * blockDim.x + threadIdx.x) >> 5);
    const int lane = threadIdx.x & 31;
    if (warp >= M) return;

    const int start = g_bounds[warp];
    const int end   = g_bounds[warp + 1];
    const int cnt   = end - start;

    // Row = 128 floats = 32 float4; lane l owns columns [4l, 4l+4).
    const float4* p = reinterpret_cast<const float4*>(msgs)
                      + (size_t)start * 32 + lane;

    float4 acc = make_float4(0.f, 0.f, 0.f, 0.f);
    int n = cnt;
    // 4-way unrolled: 4 independent LDG.128 in flight per warp
    while (n >= 4) {
        float4 a = p[0];
        float4 b = p[32];
        float4 c = p[64];
        float4 d = p[96];
        acc.x += (a.x + b.x) + (c.x + d.x);
        acc.y += (a.y + b.y) + (c.y + d.y);
        acc.z += (a.z + b.z) + (c.z + d.z);
        acc.w += (a.w + b.w) + (c.w + d.w);
        p += 128;
        n -= 4;
    }
    while (n > 0) {
        float4 a = p[0];
        acc.x += a.x; acc.y += a.y; acc.z += a.z; acc.w += a.w;
        p += 32;
        n -= 1;
    }

    const float inv = 1.0f / fmaxf((float)cnt, 1.0f);
    acc.x *= inv; acc.y *= inv; acc.z *= inv; acc.w *= inv;

    float* ob = out_means + (size_t)warp * DCOLS + lane * 4;
    if ((M & 3) == 0) {
        // out_means = out + M floats; M % 4 == 0 -> 16B aligned
        *reinterpret_cast<float4*>(ob) = acc;
    } else {
        ob[0] = acc.x; ob[1] = acc.y; ob[2] = acc.z; ob[3] = acc.w;
    }
}

__global__ __launch_bounds__(256) void epi_kernel(
    const int* __restrict__ nids,
    const float* __restrict__ ts,
    float* __restrict__ out,
    int M)
{
    const int s = blockIdx.x * blockDim.x + threadIdx.x;
    if (s >= M) return;
    out[s] = (float)nids[s];
    const int b = g_bounds[s];
    const int e = g_bounds[s + 1];
    const int idx = (e > b) ? (e - 1) : 0;   // ref clips empty-segment index to 0
    out[(size_t)M * (DCOLS + 1) + s] = ts[idx];
}

extern "C" void kernel_launch(void* const* d_in, const int* in_sizes, int n_in,
                              void* d_out, int out_size)
{
    const int*   nids = (const int*)d_in[0];
    const float* msgs = (const float*)d_in[1];
    const float* ts   = (const float*)d_in[2];
    const int*   seg  = (const int*)d_in[3];
    float* out = (float*)d_out;

    const int M = in_sizes[0];
    const int N = in_sizes[2];

    // K1: segment bounds
    bounds_kernel<<<(M + 1 + 255) / 256, 256>>>(seg, N, M);

    // K2: warp-per-segment means (M warps = M*32 threads)
    const long long threads = (long long)M * 32;
    mean_kernel<<<(unsigned)((threads + 255) / 256), 256>>>(msgs, out + M, M);

    // K3: nids + last timestamps
    epi_kernel<<<(M + 255) / 256, 256>>>(nids, ts, out, M);
}

// round 3
// speedup vs baseline: 2.8542x; 1.0088x over previous
#include <cuda_runtime.h>
#include <cuda_bf16.h>

// MeanMemoryMessageReducer — segment mean + last timestamp, sorted segment_ids.
//
// 2-kernel pipeline:
//   K1 bounds_scan : one pass over seg[]; transition positions give
//                    bounds[s] = lower_bound(seg, s) directly (no binary search)
//   K2 mean_kernel : warp-per-segment, float4 row loads with streaming hints,
//                    fused epilogue (nids cast + last-timestamp) on lane 0
//
// Output layout (float32): [ nids(M) | means(M*128) | last_ts(M) ]

#define DCOLS 128
#define MAX_M (1 << 20)

__device__ int g_bounds[MAX_M + 1];

// bounds[s] = first index i with seg[i] >= s.
// For each transition seg[i-1] < seg[i], every s in (seg[i-1], seg[i]] has
// bounds[s] = i. Head: s in [0, seg[0]] -> 0. Tail: s in (seg[N-1], M] -> N.
__global__ __launch_bounds__(256) void bounds_scan(
    const int* __restrict__ seg, int N, int M)
{
    const int i = blockIdx.x * blockDim.x + threadIdx.x;
    if (i >= N) return;

    const int cur  = seg[i];
    const int prev = (i == 0) ? -1 : seg[i - 1];

    for (int s = prev + 1; s <= cur; ++s)
        g_bounds[s] = i;

    if (i == N - 1) {
        for (int s = cur + 1; s <= M; ++s)
            g_bounds[s] = N;
    }
}

__global__ __launch_bounds__(256) void mean_kernel(
    const float* __restrict__ msgs,
    const int*   __restrict__ nids,
    const float* __restrict__ ts,
    float* __restrict__ out,
    int M, int vec_ok)
{
    const int warp = (int)((blockIdx.x * blockDim.x + threadIdx.x) >> 5);
    const int lane = threadIdx.x & 31;
    if (warp >= M) return;

    const int start = g_bounds[warp];
    const int end   = g_bounds[warp + 1];
    const int cnt   = end - start;

    // Fused epilogue: nid cast + last timestamp (ref clips empty-seg idx to 0)
    if (lane == 0) {
        out[warp] = (float)nids[warp];
        const int idx = (cnt > 0) ? (end - 1) : 0;
        out[(size_t)M * (DCOLS + 1) + warp] = ts[idx];
    }

    // Row = 128 floats = 32 float4; lane l owns columns [4l, 4l+4).
    const float4* p = reinterpret_cast<const float4*>(msgs)
                      + (size_t)start * 32 + lane;

    float4 acc = make_float4(0.f, 0.f, 0.f, 0.f);
    int n = cnt;
    while (n >= 4) {                       // 4 independent LDG.128 in flight
        float4 a = __ldcs(p);
        float4 b = __ldcs(p + 32);
        float4 c = __ldcs(p + 64);
        float4 d = __ldcs(p + 96);
        acc.x += (a.x + b.x) + (c.x + d.x);
        acc.y += (a.y + b.y) + (c.y + d.y);
        acc.z += (a.z + b.z) + (c.z + d.z);
        acc.w += (a.w + b.w) + (c.w + d.w);
        p += 128;
        n -= 4;
    }
    while (n > 0) {
        float4 a = __ldcs(p);
        acc.x += a.x; acc.y += a.y; acc.z += a.z; acc.w += a.w;
        p += 32;
        n -= 1;
    }

    const float inv = 1.0f / fmaxf((float)cnt, 1.0f);
    acc.x *= inv; acc.y *= inv; acc.z *= inv; acc.w *= inv;

    float* ob = out + (size_t)M + (size_t)warp * DCOLS + lane * 4;
    if (vec_ok) {
        __stcs(reinterpret_cast<float4*>(ob), acc);
    } else {
        ob[0] = acc.x; ob[1] = acc.y; ob[2] = acc.z; ob[3] = acc.w;
    }
}

extern "C" void kernel_launch(void* const* d_in, const int* in_sizes, int n_in,
                              void* d_out, int out_size)
{
    const int*   nids = (const int*)d_in[0];
    const float* msgs = (const float*)d_in[1];
    const float* ts   = (const float*)d_in[2];
    const int*   seg  = (const int*)d_in[3];
    float* out = (float*)d_out;

    const int M = in_sizes[0];
    const int N = in_sizes[2];
    const int vec_ok = ((M & 3) == 0) ? 1 : 0;   // out+M 16B-aligned

    bounds_scan<<<(N + 255) / 256, 256>>>(seg, N, M);

    const long long threads = (long long)M * 32;
    mean_kernel<<<(unsigned)((threads + 255) / 256), 256>>>(
        msgs, nids, ts, out, M, vec_ok);
}

// round 4
// speedup vs baseline: 2.8879x; 1.0118x over previous
#include <cuda_runtime.h>
#include <cuda_bf16.h>

// MeanMemoryMessageReducer — segment mean + last timestamp, sorted segment_ids.
//
// 2-kernel pipeline:
//   K1 bounds_scan_v4 : int4-vectorized transition scan over seg[];
//                       bounds[s] = lower_bound(seg, s) without binary search
//   K2 mean_kernel    : warp-per-segment, float4 row loads with streaming hints,
//                       fused epilogue (nids cast + last-timestamp) on lane 0
//
// Output layout (float32): [ nids(M) | means(M*128) | last_ts(M) ]

#define DCOLS 128
#define MAX_M (1 << 20)

__device__ int g_bounds[MAX_M + 1];

// Each thread covers positions [4i, 4i+4). For every adjacent pair (p, c) with
// p < c, all s in (p, c] get bounds[s] = index of c. Head uses prev = -1.
// The thread owning the final element fills (seg[N-1], M] with N.
__global__ __launch_bounds__(256) void bounds_scan_v4(
    const int* __restrict__ seg, int N, int M)
{
    const int i = blockIdx.x * blockDim.x + threadIdx.x;
    const int base = i * 4;
    if (base >= N) return;

    int vals[4];
    if (base + 3 < N) {
        const int4 v = *reinterpret_cast<const int4*>(seg + base);
        vals[0] = v.x; vals[1] = v.y; vals[2] = v.z; vals[3] = v.w;
    } else {
        #pragma unroll
        for (int j = 0; j < 4; ++j)
            vals[j] = (base + j < N) ? seg[base + j] : vals[j > 0 ? j - 1 : 0];
    }

    int p = (base == 0) ? -1 : seg[base - 1];   // L2/L1 hit (neighbor's data)

    const int lim = (base + 4 <= N) ? 4 : (N - base);
    #pragma unroll
    for (int j = 0; j < 4; ++j) {
        if (j < lim) {
            const int c = vals[j];
            for (int s = p + 1; s <= c; ++s)
                g_bounds[s] = base + j;
            p = c;
        }
    }

    if (base + lim == N) {                       // owns the last element
        for (int s = p + 1; s <= M; ++s)
            g_bounds[s] = N;
    }
}

__global__ __launch_bounds__(256) void mean_kernel(
    const float* __restrict__ msgs,
    const int*   __restrict__ nids,
    const float* __restrict__ ts,
    float* __restrict__ out,
    int M, int vec_ok)
{
    const int warp = (int)((blockIdx.x * blockDim.x + threadIdx.x) >> 5);
    const int lane = threadIdx.x & 31;
    if (warp >= M) return;

    const int start = __ldg(&g_bounds[warp]);
    const int end   = __ldg(&g_bounds[warp + 1]);
    const int cnt   = end - start;

    // Fused epilogue: nid cast + last timestamp (ref clips empty-seg idx to 0)
    if (lane == 0) {
        out[warp] = (float)nids[warp];
        const int idx = (cnt > 0) ? (end - 1) : 0;
        out[(size_t)M * (DCOLS + 1) + warp] = ts[idx];
    }

    // Row = 128 floats = 32 float4; lane l owns columns [4l, 4l+4).
    const float4* p = reinterpret_cast<const float4*>(msgs)
                      + (size_t)start * 32 + lane;

    float4 acc = make_float4(0.f, 0.f, 0.f, 0.f);
    int n = cnt;
    while (n >= 4) {                       // 4 independent LDG.128 in flight
        float4 a = __ldcs(p);
        float4 b = __ldcs(p + 32);
        float4 c = __ldcs(p + 64);
        float4 d = __ldcs(p + 96);
        acc.x += (a.x + b.x) + (c.x + d.x);
        acc.y += (a.y + b.y) + (c.y + d.y);
        acc.z += (a.z + b.z) + (c.z + d.z);
        acc.w += (a.w + b.w) + (c.w + d.w);
        p += 128;
        n -= 4;
    }
    while (n > 0) {
        float4 a = __ldcs(p);
        acc.x += a.x; acc.y += a.y; acc.z += a.z; acc.w += a.w;
        p += 32;
        n -= 1;
    }

    const float inv = 1.0f / fmaxf((float)cnt, 1.0f);
    acc.x *= inv; acc.y *= inv; acc.z *= inv; acc.w *= inv;

    float* ob = out + (size_t)M + (size_t)warp * DCOLS + lane * 4;
    if (vec_ok) {
        __stcs(reinterpret_cast<float4*>(ob), acc);
    } else {
        ob[0] = acc.x; ob[1] = acc.y; ob[2] = acc.z; ob[3] = acc.w;
    }
}

extern "C" void kernel_launch(void* const* d_in, const int* in_sizes, int n_in,
                              void* d_out, int out_size)
{
    const int*   nids = (const int*)d_in[0];
    const float* msgs = (const float*)d_in[1];
    const float* ts   = (const float*)d_in[2];
    const int*   seg  = (const int*)d_in[3];
    float* out = (float*)d_out;

    const int M = in_sizes[0];
    const int N = in_sizes[2];
    const int vec_ok = ((M & 3) == 0) ? 1 : 0;   // out+M 16B-aligned

    const int n4 = (N + 3) / 4;
    bounds_scan_v4<<<(n4 + 255) / 256, 256>>>(seg, N, M);

    const long long threads = (long long)M * 32;
    mean_kernel<<<(unsigned)((threads + 255) / 256), 256>>>(
        msgs, nids, ts, out, M, vec_ok);
}